// round 1
// baseline (speedup 1.0000x reference)
#include <cuda_runtime.h>

// Problem constants
#define BT      524288
#define D_IN    64
#define NG      8     // groups
#define NF      8     // features/group
#define NE      4     // encoder dim
#define NA      8     // attention dim
#define NHD     2     // heads
#define H1      128
#define H2      32
#define NOUT    2

#define ROWS      64
#define NTHREADS  512
#define NBLOCKS   (BT / ROWS)

#define XS_STRIDE 68
#define H1_STRIDE 129

// shared layout (float offsets)
#define OFF_XS   0            // [64][68]
#define OFF_W1   4352         // [64][128]
#define OFF_H1   12544        // [64][129]
#define OFF_W2   20800        // [128][32]
#define OFF_HS   24896        // [64][33]
#define OFF_AT   27008        // [64][33]
#define OFF_H2   29120        // [64][33]
#define OFF_MEAN 31232        // [64]
#define OFF_INV  31296        // [64]
#define SMEM_FLOATS 31360
#define SMEM_BYTES  (SMEM_FLOATS * 4)

__global__ __launch_bounds__(NTHREADS)
void ggat_kernel(
    const float* __restrict__ x,
    const float* __restrict__ norm_mean,
    const float* __restrict__ norm_std,
    const float* __restrict__ w1, const float* __restrict__ b1,
    const float* __restrict__ w2, const float* __restrict__ b2,
    const float* __restrict__ enc_w, const float* __restrict__ enc_b,
    const float* __restrict__ src_w, const float* __restrict__ src_b,
    const float* __restrict__ dst_w, const float* __restrict__ dst_b,
    const float* __restrict__ dec_w, const float* __restrict__ dec_b,
    float* __restrict__ out)
{
    extern __shared__ float smem[];
    float* xs  = smem + OFF_XS;
    float* w1s = smem + OFF_W1;
    float* h1s = smem + OFF_H1;
    float* w2s = smem + OFF_W2;
    float* hs  = smem + OFF_HS;
    float* ats = smem + OFF_AT;
    float* h2s = smem + OFF_H2;
    float* msh = smem + OFF_MEAN;
    float* ish = smem + OFF_INV;

    const int t    = threadIdx.x;
    const int row0 = blockIdx.x * ROWS;

    // ---------------- Phase 0: cooperative loads ----------------
    {
        const float4* xg = (const float4*)(x + (size_t)row0 * D_IN);
        #pragma unroll
        for (int i = t; i < ROWS * D_IN / 4; i += NTHREADS) {
            float4 v = xg[i];
            ((float4*)xs)[(i >> 4) * 17 + (i & 15)] = v;   // 17 float4 = 68 floats stride
        }
        const float4* w1g = (const float4*)w1;
        #pragma unroll
        for (int i = t; i < D_IN * H1 / 4; i += NTHREADS) ((float4*)w1s)[i] = w1g[i];
        const float4* w2g = (const float4*)w2;
        #pragma unroll
        for (int i = t; i < H1 * H2 / 4; i += NTHREADS) ((float4*)w2s)[i] = w2g[i];
        if (t < D_IN) {
            msh[t] = norm_mean[t];
            ish[t] = 1.0f / (norm_std[t] + 1e-8f);
        }
    }
    __syncthreads();

    // ---------------- Phase 1: MLP layer 1  h1 = relu(x @ w1 + b1) ----------------
    {
        const int tr = t >> 4;        // 0..31 -> rows tr*2, tr*2+1
        const int tc = t & 15;        // 0..15 -> cols tc*8 .. +7
        const int r0 = tr * 2;
        const int c0 = tc * 8;
        float acc0[8], acc1[8];
        #pragma unroll
        for (int j = 0; j < 8; j++) { acc0[j] = 0.f; acc1[j] = 0.f; }

        #pragma unroll 8
        for (int k = 0; k < D_IN; k++) {
            float a0 = xs[r0 * XS_STRIDE + k];
            float a1 = xs[(r0 + 1) * XS_STRIDE + k];
            float4 bA = *(const float4*)&w1s[k * H1 + c0];
            float4 bB = *(const float4*)&w1s[k * H1 + c0 + 4];
            acc0[0] += a0 * bA.x; acc1[0] += a1 * bA.x;
            acc0[1] += a0 * bA.y; acc1[1] += a1 * bA.y;
            acc0[2] += a0 * bA.z; acc1[2] += a1 * bA.z;
            acc0[3] += a0 * bA.w; acc1[3] += a1 * bA.w;
            acc0[4] += a0 * bB.x; acc1[4] += a1 * bB.x;
            acc0[5] += a0 * bB.y; acc1[5] += a1 * bB.y;
            acc0[6] += a0 * bB.z; acc1[6] += a1 * bB.z;
            acc0[7] += a0 * bB.w; acc1[7] += a1 * bB.w;
        }
        #pragma unroll
        for (int j = 0; j < 8; j++) {
            float bb = __ldg(&b1[c0 + j]);
            h1s[r0 * H1_STRIDE + c0 + j]       = fmaxf(acc0[j] + bb, 0.f);
            h1s[(r0 + 1) * H1_STRIDE + c0 + j] = fmaxf(acc1[j] + bb, 0.f);
        }
    }

    // ---------------- Phase 1b: group encoder  h = relu(xn_g @ enc_w_g + enc_b_g) ----
    // independent of h1 (only needs xs) — do before the sync
    {
        const int row = t >> 3;       // 0..63
        const int g   = t & 7;        // 0..7
        float xn[NF];
        #pragma unroll
        for (int f = 0; f < NF; f++) {
            int k = g * NF + f;
            xn[f] = (xs[row * XS_STRIDE + k] - msh[k]) * ish[k];
        }
        #pragma unroll
        for (int e = 0; e < NE; e++) {
            float acc = __ldg(&enc_b[g * NE + e]);
            #pragma unroll
            for (int f = 0; f < NF; f++)
                acc += xn[f] * __ldg(&enc_w[(g * NF + f) * NE + e]);
            hs[row * 33 + g * NE + e] = fmaxf(acc, 0.f);
        }
    }
    __syncthreads();

    // ---------------- Phase 2: MLP layer 2  h2 = relu(h1 @ w2 + b2) ----------------
    {
        const int rg = t >> 3;        // 0..63 (row)
        const int cg = (t & 7) * 4;   // col base
        float acc[4] = {0.f, 0.f, 0.f, 0.f};
        #pragma unroll 16
        for (int k = 0; k < H1; k++) {
            float a  = h1s[rg * H1_STRIDE + k];
            float4 b = *(const float4*)&w2s[k * H2 + cg];
            acc[0] += a * b.x; acc[1] += a * b.y;
            acc[2] += a * b.z; acc[3] += a * b.w;
        }
        #pragma unroll
        for (int j = 0; j < 4; j++)
            h2s[rg * 33 + cg + j] = fmaxf(acc[j] + __ldg(&b2[cg + j]), 0.f);
    }

    // ---------------- Phase 3: 2-head GAT attention over the 8 group nodes --------
    // warp handles 2 rows; lane = (row2, head, group)
    {
        const int warp = t >> 5;      // 0..15
        const int lane = t & 31;
        const int r2   = lane >> 4;         // 0/1
        const int hd   = (lane >> 3) & 1;   // head
        const int g    = lane & 7;          // group
        #pragma unroll
        for (int it = 0; it < 2; it++) {
            const int row = (it * 16 + warp) * 2 + r2;

            float hg[NE];
            #pragma unroll
            for (int e = 0; e < NE; e++) hg[e] = hs[row * 33 + g * NE + e];

            float sr[NA], ds[NA];
            #pragma unroll
            for (int a = 0; a < NA; a++) {
                float s = __ldg(&src_b[hd * NA + a]);
                float d = __ldg(&dst_b[hd * NA + a]);
                #pragma unroll
                for (int e = 0; e < NE; e++) {
                    s += hg[e] * __ldg(&src_w[e * (NHD * NA) + hd * NA + a]);
                    d += hg[e] * __ldg(&dst_w[e * (NHD * NA) + hd * NA + a]);
                }
                sr[a] = s; ds[a] = d;
            }

            // scores[g][k] = <src_g, dst_k> / sqrt(A); dst_k fetched via shfl
            float sc[NA];
            #pragma unroll
            for (int k = 0; k < NA; k++) {
                float s = 0.f;
                const int srcl = (lane & 24) | k;   // same (r2, hd), group k
                #pragma unroll
                for (int a = 0; a < NA; a++)
                    s += sr[a] * __shfl_sync(0xffffffffu, ds[a], srcl);
                sc[k] = s * 0.35355339059327373f;   // 1/sqrt(8)
            }

            // softmax over k (in registers)
            float m = sc[0];
            #pragma unroll
            for (int k = 1; k < NA; k++) m = fmaxf(m, sc[k]);
            float sum = 0.f;
            #pragma unroll
            for (int k = 0; k < NA; k++) { sc[k] = __expf(sc[k] - m); sum += sc[k]; }
            const float invs = 1.f / sum;

            // att partial for this head: sum_k p_k * h[k][e]
            float acc[NE] = {0.f, 0.f, 0.f, 0.f};
            #pragma unroll
            for (int k = 0; k < NA; k++) {
                float p = sc[k] * invs;
                #pragma unroll
                for (int e = 0; e < NE; e++)
                    acc[e] += p * hs[row * 33 + k * NE + e];
            }
            // reduce the two heads (lane bit 3), lane hd==0 writes
            #pragma unroll
            for (int e = 0; e < NE; e++) {
                float tot = acc[e] + __shfl_xor_sync(0xffffffffu, acc[e], 8);
                if (hd == 0) ats[row * 33 + g * NE + e] = tot;
            }
        }
    }
    __syncthreads();

    // ---------------- Phase 4: decoder  out = [h2 | h | att] @ dec_w + dec_b ------
    if (t < ROWS * NOUT) {
        const int row = t >> 1;
        const int o   = t & 1;
        float acc = __ldg(&dec_b[o]);
        #pragma unroll
        for (int i = 0; i < 32; i++) acc += h2s[row * 33 + i] * __ldg(&dec_w[i * NOUT + o]);
        #pragma unroll
        for (int i = 0; i < 32; i++) acc += hs[row * 33 + i]  * __ldg(&dec_w[(32 + i) * NOUT + o]);
        #pragma unroll
        for (int i = 0; i < 32; i++) acc += ats[row * 33 + i] * __ldg(&dec_w[(64 + i) * NOUT + o]);
        out[(size_t)(row0 + row) * NOUT + o] = acc;
    }
}

extern "C" void kernel_launch(void* const* d_in, const int* in_sizes, int n_in,
                              void* d_out, int out_size)
{
    const float* x         = (const float*)d_in[0];
    const float* norm_mean = (const float*)d_in[1];
    const float* norm_std  = (const float*)d_in[2];
    const float* w1        = (const float*)d_in[3];
    const float* b1        = (const float*)d_in[4];
    const float* w2        = (const float*)d_in[5];
    const float* b2        = (const float*)d_in[6];
    const float* enc_w     = (const float*)d_in[7];
    const float* enc_b     = (const float*)d_in[8];
    const float* src_w     = (const float*)d_in[9];
    const float* src_b     = (const float*)d_in[10];
    const float* dst_w     = (const float*)d_in[11];
    const float* dst_b     = (const float*)d_in[12];
    const float* dec_w     = (const float*)d_in[13];
    const float* dec_b     = (const float*)d_in[14];
    float* out = (float*)d_out;

    cudaFuncSetAttribute(ggat_kernel,
                         cudaFuncAttributeMaxDynamicSharedMemorySize, SMEM_BYTES);
    ggat_kernel<<<NBLOCKS, NTHREADS, SMEM_BYTES>>>(
        x, norm_mean, norm_std, w1, b1, w2, b2,
        enc_w, enc_b, src_w, src_b, dst_w, dst_b, dec_w, dec_b, out);
}

// round 2
// speedup vs baseline: 1.3768x; 1.3768x over previous
#include <cuda_runtime.h>

// Problem constants
#define BT      524288
#define D_IN    64
#define NG      8
#define NF      8
#define NE      4
#define NA      8
#define NHD     2
#define H1      128
#define H2      32
#define NOUT    2

#define ROWS      64
#define NTHREADS  512
#define NBLOCKS   (BT / ROWS)

#define XS_STRIDE 68
#define H1_STRIDE 132
#define SS        36            // stride for hs/ats/h2s (float4-aligned)

// shared layout (float offsets, all 16B aligned)
#define OFF_XS    0             // [64][68]      4352
#define OFF_W1    4352          // [64][128]     8192
#define OFF_H1    12544         // [64][132]     8448
#define OFF_W2    20992         // [128][32]     4096
#define OFF_HS    25088         // [64][36]      2304
#define OFF_AT    27392         // [64][36]      2304
#define OFF_H2    29696         // [64][36]      2304
#define OFF_MEAN  32000         // 64
#define OFF_INV   32064         // 64
#define OFF_B1    32128         // 128
#define OFF_B2    32256         // 32
#define OFF_SRCW  32288         // 64
#define OFF_DSTW  32352         // 64
#define OFF_SRCB  32416         // 16
#define OFF_DSTB  32432         // 16
#define OFF_ENCW  32448         // 256
#define OFF_ENCB  32704         // 32
#define OFF_DECW  32736         // 192 (transposed [2][96])
#define OFF_DECB  32928         // 4
#define SMEM_FLOATS 32932
#define SMEM_BYTES  (SMEM_FLOATS * 4)

typedef unsigned long long u64;

__device__ __forceinline__ u64 pack2(float x, float y) {
    u64 r; asm("mov.b64 %0,{%1,%2};" : "=l"(r) : "f"(x), "f"(y)); return r;
}
__device__ __forceinline__ u64 ffma2(u64 a, u64 b, u64 c) {
    u64 d; asm("fma.rn.f32x2 %0,%1,%2,%3;" : "=l"(d) : "l"(a), "l"(b), "l"(c)); return d;
}
__device__ __forceinline__ float2 unpack2(u64 v) {
    float2 f; asm("mov.b64 {%0,%1},%2;" : "=f"(f.x), "=f"(f.y) : "l"(v)); return f;
}

__global__ __launch_bounds__(NTHREADS)
void ggat_kernel(
    const float* __restrict__ x,
    const float* __restrict__ norm_mean,
    const float* __restrict__ norm_std,
    const float* __restrict__ w1, const float* __restrict__ b1,
    const float* __restrict__ w2, const float* __restrict__ b2,
    const float* __restrict__ enc_w, const float* __restrict__ enc_b,
    const float* __restrict__ src_w, const float* __restrict__ src_b,
    const float* __restrict__ dst_w, const float* __restrict__ dst_b,
    const float* __restrict__ dec_w, const float* __restrict__ dec_b,
    float* __restrict__ out)
{
    extern __shared__ float smem[];
    float* xs   = smem + OFF_XS;
    float* w1s  = smem + OFF_W1;
    float* h1s  = smem + OFF_H1;
    float* w2s  = smem + OFF_W2;
    float* hs   = smem + OFF_HS;
    float* ats  = smem + OFF_AT;
    float* h2s  = smem + OFF_H2;

    const int t    = threadIdx.x;
    const int row0 = blockIdx.x * ROWS;

    // ---------------- Phase 0: cooperative staging ----------------
    {
        const float4* xg = (const float4*)(x + (size_t)row0 * D_IN);
        #pragma unroll
        for (int i = t; i < ROWS * D_IN / 4; i += NTHREADS) {
            float4 v = xg[i];
            ((float4*)xs)[(i >> 4) * 17 + (i & 15)] = v;
        }
        const float4* w1g = (const float4*)w1;
        #pragma unroll
        for (int i = t; i < D_IN * H1 / 4; i += NTHREADS) ((float4*)w1s)[i] = w1g[i];
        const float4* w2g = (const float4*)w2;
        #pragma unroll
        for (int i = t; i < H1 * H2 / 4; i += NTHREADS) ((float4*)w2s)[i] = w2g[i];
        if (t < D_IN) {
            smem[OFF_MEAN + t] = norm_mean[t];
            smem[OFF_INV + t]  = 1.0f / (norm_std[t] + 1e-8f);
        }
        if (t < H1)  smem[OFF_B1 + t]   = b1[t];
        if (t < H2)  smem[OFF_B2 + t]   = b2[t];
        if (t < 64)  smem[OFF_SRCW + t] = src_w[t];
        if (t < 64)  smem[OFF_DSTW + t] = dst_w[t];
        if (t < 16)  smem[OFF_SRCB + t] = src_b[t];
        if (t < 16)  smem[OFF_DSTB + t] = dst_b[t];
        if (t < 256) smem[OFF_ENCW + t] = enc_w[t];
        if (t < 32)  smem[OFF_ENCB + t] = enc_b[t];
        if (t < 192) smem[OFF_DECW + (t & 1) * 96 + (t >> 1)] = dec_w[t]; // transpose
        if (t < 2)   smem[OFF_DECB + t] = dec_b[t];
    }
    __syncthreads();

    if (t < 256) {
        // ---------- Phase 1: MLP1  h1 = relu(x @ w1 + b1), 4x8 register tiles ----
        const int rg = t >> 4;        // 0..15 -> rows rg*4 .. +3
        const int cg = t & 15;        // cols cg*8 .. +7
        const int r0 = rg * 4;
        const int c0 = cg * 8;
        u64 acc[4][4];
        #pragma unroll
        for (int i = 0; i < 4; i++)
            #pragma unroll
            for (int j = 0; j < 4; j++) acc[i][j] = 0ull;

        #pragma unroll 16
        for (int k = 0; k < D_IN; k++) {
            ulonglong2 wA = *(const ulonglong2*)&w1s[k * H1 + c0];
            ulonglong2 wB = *(const ulonglong2*)&w1s[k * H1 + c0 + 4];
            #pragma unroll
            for (int i = 0; i < 4; i++) {
                float a = xs[(r0 + i) * XS_STRIDE + k];
                u64 ap = pack2(a, a);
                acc[i][0] = ffma2(ap, wA.x, acc[i][0]);
                acc[i][1] = ffma2(ap, wA.y, acc[i][1]);
                acc[i][2] = ffma2(ap, wB.x, acc[i][2]);
                acc[i][3] = ffma2(ap, wB.y, acc[i][3]);
            }
        }
        float4 bA = *(const float4*)&smem[OFF_B1 + c0];
        float4 bB = *(const float4*)&smem[OFF_B1 + c0 + 4];
        #pragma unroll
        for (int i = 0; i < 4; i++) {
            float2 u0 = unpack2(acc[i][0]);
            float2 u1 = unpack2(acc[i][1]);
            float2 u2 = unpack2(acc[i][2]);
            float2 u3 = unpack2(acc[i][3]);
            float4 o0 = make_float4(fmaxf(u0.x + bA.x, 0.f), fmaxf(u0.y + bA.y, 0.f),
                                    fmaxf(u1.x + bA.z, 0.f), fmaxf(u1.y + bA.w, 0.f));
            float4 o1 = make_float4(fmaxf(u2.x + bB.x, 0.f), fmaxf(u2.y + bB.y, 0.f),
                                    fmaxf(u3.x + bB.z, 0.f), fmaxf(u3.y + bB.w, 0.f));
            *(float4*)&h1s[(r0 + i) * H1_STRIDE + c0]     = o0;
            *(float4*)&h1s[(r0 + i) * H1_STRIDE + c0 + 4] = o1;
        }
    } else {
        // ---------- Phase 1b: group encoder (runs concurrently on warps 8-15) ----
        const int t2 = t - 256;
        #pragma unroll
        for (int it = 0; it < 2; it++) {
            const int task = t2 + it * 256;
            const int row  = task >> 3;
            const int g    = task & 7;
            const int base = g * 8;
            float4 xa = *(const float4*)&xs[row * XS_STRIDE + base];
            float4 xb = *(const float4*)&xs[row * XS_STRIDE + base + 4];
            float4 ma = *(const float4*)&smem[OFF_MEAN + base];
            float4 mb = *(const float4*)&smem[OFF_MEAN + base + 4];
            float4 ia = *(const float4*)&smem[OFF_INV + base];
            float4 ib = *(const float4*)&smem[OFF_INV + base + 4];
            float xn[8];
            xn[0] = (xa.x - ma.x) * ia.x; xn[1] = (xa.y - ma.y) * ia.y;
            xn[2] = (xa.z - ma.z) * ia.z; xn[3] = (xa.w - ma.w) * ia.w;
            xn[4] = (xb.x - mb.x) * ib.x; xn[5] = (xb.y - mb.y) * ib.y;
            xn[6] = (xb.z - mb.z) * ib.z; xn[7] = (xb.w - mb.w) * ib.w;

            ulonglong2 eb = *(const ulonglong2*)&smem[OFF_ENCB + g * 4];
            u64 e01 = eb.x, e23 = eb.y;
            #pragma unroll
            for (int f = 0; f < 8; f++) {
                ulonglong2 wf = *(const ulonglong2*)&smem[OFF_ENCW + (base + f) * 4];
                u64 xp = pack2(xn[f], xn[f]);
                e01 = ffma2(xp, wf.x, e01);
                e23 = ffma2(xp, wf.y, e23);
            }
            float2 v01 = unpack2(e01), v23 = unpack2(e23);
            float4 hv = make_float4(fmaxf(v01.x, 0.f), fmaxf(v01.y, 0.f),
                                    fmaxf(v23.x, 0.f), fmaxf(v23.y, 0.f));
            *(float4*)&hs[row * SS + g * 4] = hv;
        }
    }
    __syncthreads();

    // ---------------- Phase 2: MLP2  h2 = relu(h1 @ w2 + b2) ----------------
    {
        const int rg = t >> 3;          // row
        const int cg = (t & 7) * 4;     // col base
        u64 c01 = 0ull, c23 = 0ull;
        #pragma unroll 8
        for (int k = 0; k < H1; k++) {
            float a = h1s[rg * H1_STRIDE + k];
            ulonglong2 w = *(const ulonglong2*)&w2s[k * H2 + cg];
            u64 ap = pack2(a, a);
            c01 = ffma2(ap, w.x, c01);
            c23 = ffma2(ap, w.y, c23);
        }
        float4 bb = *(const float4*)&smem[OFF_B2 + cg];
        float2 u0 = unpack2(c01), u1 = unpack2(c23);
        float4 o = make_float4(fmaxf(u0.x + bb.x, 0.f), fmaxf(u0.y + bb.y, 0.f),
                               fmaxf(u1.x + bb.z, 0.f), fmaxf(u1.y + bb.w, 0.f));
        *(float4*)&h2s[rg * SS + cg] = o;
    }

    // ---------------- Phase 3: 2-head GAT over 8 group nodes ----------------
    // independent of phase 2 -> no sync. warp lane = (r2, head, group)
    {
        const int warp = t >> 5;
        const int lane = t & 31;
        const int r2   = lane >> 4;
        const int hd   = (lane >> 3) & 1;
        const int g    = lane & 7;
        #pragma unroll
        for (int it = 0; it < 2; it++) {
            const int row = (it * 16 + warp) * 2 + r2;

            float4 hg = *(const float4*)&hs[row * SS + g * 4];
            float  hge[4] = {hg.x, hg.y, hg.z, hg.w};

            ulonglong2 sb0 = *(const ulonglong2*)&smem[OFF_SRCB + hd * 8];
            ulonglong2 db0 = *(const ulonglong2*)&smem[OFF_DSTB + hd * 8];
            u64 sp[4] = {sb0.x, sb0.y, 0ull, 0ull};
            u64 dp[4] = {db0.x, db0.y, 0ull, 0ull};
            {
                ulonglong2 sb1 = *(const ulonglong2*)&smem[OFF_SRCB + hd * 8 + 4];
                ulonglong2 db1 = *(const ulonglong2*)&smem[OFF_DSTB + hd * 8 + 4];
                sp[2] = sb1.x; sp[3] = sb1.y;
                dp[2] = db1.x; dp[3] = db1.y;
            }
            #pragma unroll
            for (int e = 0; e < NE; e++) {
                u64 hp = pack2(hge[e], hge[e]);
                ulonglong2 sv0 = *(const ulonglong2*)&smem[OFF_SRCW + e * 16 + hd * 8];
                ulonglong2 sv1 = *(const ulonglong2*)&smem[OFF_SRCW + e * 16 + hd * 8 + 4];
                ulonglong2 dv0 = *(const ulonglong2*)&smem[OFF_DSTW + e * 16 + hd * 8];
                ulonglong2 dv1 = *(const ulonglong2*)&smem[OFF_DSTW + e * 16 + hd * 8 + 4];
                sp[0] = ffma2(hp, sv0.x, sp[0]); sp[1] = ffma2(hp, sv0.y, sp[1]);
                sp[2] = ffma2(hp, sv1.x, sp[2]); sp[3] = ffma2(hp, sv1.y, sp[3]);
                dp[0] = ffma2(hp, dv0.x, dp[0]); dp[1] = ffma2(hp, dv0.y, dp[1]);
                dp[2] = ffma2(hp, dv1.x, dp[2]); dp[3] = ffma2(hp, dv1.y, dp[3]);
            }
            float sr[NA], ds[NA];
            #pragma unroll
            for (int j = 0; j < 4; j++) {
                float2 s = unpack2(sp[j]); sr[2*j] = s.x; sr[2*j+1] = s.y;
                float2 d = unpack2(dp[j]); ds[2*j] = d.x; ds[2*j+1] = d.y;
            }

            float sc[NA];
            #pragma unroll
            for (int k = 0; k < NA; k++) {
                float s = 0.f;
                const int srcl = (lane & 24) | k;
                #pragma unroll
                for (int a = 0; a < NA; a++)
                    s += sr[a] * __shfl_sync(0xffffffffu, ds[a], srcl);
                sc[k] = s * 0.35355339059327373f;
            }
            float m = sc[0];
            #pragma unroll
            for (int k = 1; k < NA; k++) m = fmaxf(m, sc[k]);
            float sum = 0.f;
            #pragma unroll
            for (int k = 0; k < NA; k++) { sc[k] = __expf(sc[k] - m); sum += sc[k]; }
            const float invs = 1.f / sum;

            u64 a01 = 0ull, a23 = 0ull;
            #pragma unroll
            for (int k = 0; k < NA; k++) {
                float p = sc[k] * invs;
                u64 pp = pack2(p, p);
                ulonglong2 hv = *(const ulonglong2*)&hs[row * SS + k * 4];
                a01 = ffma2(pp, hv.x, a01);
                a23 = ffma2(pp, hv.y, a23);
            }
            float2 u0 = unpack2(a01), u1 = unpack2(a23);
            float av[4] = {u0.x, u0.y, u1.x, u1.y};
            #pragma unroll
            for (int e = 0; e < NE; e++)
                av[e] += __shfl_xor_sync(0xffffffffu, av[e], 8);
            if (hd == 0)
                *(float4*)&ats[row * SS + g * 4] = make_float4(av[0], av[1], av[2], av[3]);
        }
    }
    __syncthreads();

    // ---------------- Phase 4: decoder ----------------
    if (t < ROWS) {
        const int row = t;
        float acc0 = smem[OFF_DECB + 0];
        float acc1 = smem[OFF_DECB + 1];
        const float* w0 = smem + OFF_DECW;        // [96] for output 0
        const float* w1t = smem + OFF_DECW + 96;  // [96] for output 1
        const float* srcs[3] = {h2s, hs, ats};
        #pragma unroll
        for (int s = 0; s < 3; s++) {
            const float* sv = srcs[s] + row * SS;
            const int off = s * 32;
            #pragma unroll
            for (int j = 0; j < 8; j++) {
                float4 v  = *(const float4*)&sv[j * 4];
                float4 wa = *(const float4*)&w0[off + j * 4];
                float4 wb = *(const float4*)&w1t[off + j * 4];
                acc0 += v.x * wa.x + v.y * wa.y + v.z * wa.z + v.w * wa.w;
                acc1 += v.x * wb.x + v.y * wb.y + v.z * wb.z + v.w * wb.w;
            }
        }
        *(float2*)&out[(size_t)(row0 + row) * NOUT] = make_float2(acc0, acc1);
    }
}

extern "C" void kernel_launch(void* const* d_in, const int* in_sizes, int n_in,
                              void* d_out, int out_size)
{
    const float* x         = (const float*)d_in[0];
    const float* norm_mean = (const float*)d_in[1];
    const float* norm_std  = (const float*)d_in[2];
    const float* w1        = (const float*)d_in[3];
    const float* b1        = (const float*)d_in[4];
    const float* w2        = (const float*)d_in[5];
    const float* b2        = (const float*)d_in[6];
    const float* enc_w     = (const float*)d_in[7];
    const float* enc_b     = (const float*)d_in[8];
    const float* src_w     = (const float*)d_in[9];
    const float* src_b     = (const float*)d_in[10];
    const float* dst_w     = (const float*)d_in[11];
    const float* dst_b     = (const float*)d_in[12];
    const float* dec_w     = (const float*)d_in[13];
    const float* dec_b     = (const float*)d_in[14];
    float* out = (float*)d_out;

    cudaFuncSetAttribute(ggat_kernel,
                         cudaFuncAttributeMaxDynamicSharedMemorySize, SMEM_BYTES);
    ggat_kernel<<<NBLOCKS, NTHREADS, SMEM_BYTES>>>(
        x, norm_mean, norm_std, w1, b1, w2, b2,
        enc_w, enc_b, src_w, src_b, dst_w, dst_b, dec_w, dec_b, out);
}

// round 4
// speedup vs baseline: 1.5579x; 1.1315x over previous
#include <cuda_runtime.h>
#include <cstdint>

#define BT       524288
#define ROWS     64
#define NTHREADS 512
#define NBLOCKS  (BT / ROWS)
#define SS       36

// ---------------- shared layout (float offsets) ----------------
// small params: [0, 1024)
#define FS_MEAN 0
#define FS_INV  64
#define FS_B1   128
#define FS_B2   256
#define FS_SRCW 288
#define FS_DSTW 352
#define FS_SRCB 416
#define FS_DSTB 432
#define FS_ENCW 448
#define FS_ENCB 704
#define FS_DECW 736      // transposed [2][96]
#define FS_DECB 928
// xs_t [64 k][68 rows]  : [1024, 5376)   -- dead after phase1; w2 [128][32] overlaid at 1024
#define F_XS   1024
#define F_W2   1024
// w1 swizzled [64][128] : [5376, 13568)  -- dead after phase1; h2s/ats overlaid
#define F_W1   5376
#define F_H2S  5376      // [64][36] = 2304
#define F_ATS  7680      // [64][36] = 2304
// h1 [64][132]          : [13568, 22016)
#define F_H1   13568
// hs [64][36]           : [22016, 24320)
#define F_HS   22016
#define SMEM_FLOATS 24320
#define SMEM_BYTES  (SMEM_FLOATS * 4)   // 97280 B -> 2 CTAs/SM

typedef unsigned long long u64;

__device__ __forceinline__ u64 pack2(float x, float y) {
    u64 r; asm("mov.b64 %0,{%1,%2};" : "=l"(r) : "f"(x), "f"(y)); return r;
}
__device__ __forceinline__ u64 ffma2(u64 a, u64 b, u64 c) {
    u64 d; asm("fma.rn.f32x2 %0,%1,%2,%3;" : "=l"(d) : "l"(a), "l"(b), "l"(c)); return d;
}
__device__ __forceinline__ float2 unpack2(u64 v) {
    float2 f; asm("mov.b64 {%0,%1},%2;" : "=f"(f.x), "=f"(f.y) : "l"(v)); return f;
}
// w1 chunk swizzle: 16B chunk c (0..31) within a 512B k-row
__device__ __host__ __forceinline__ int w1phys(int c) {
    return (c & 0x18) | ((c & 7) ^ (c >> 3));
}

__global__ __launch_bounds__(NTHREADS, 2)
void ggat_kernel(
    const float* __restrict__ x,
    const float* __restrict__ norm_mean,
    const float* __restrict__ norm_std,
    const float* __restrict__ w1g, const float* __restrict__ b1,
    const float* __restrict__ w2g, const float* __restrict__ b2,
    const float* __restrict__ enc_w, const float* __restrict__ enc_b,
    const float* __restrict__ src_w, const float* __restrict__ src_b,
    const float* __restrict__ dst_w, const float* __restrict__ dst_b,
    const float* __restrict__ dec_w, const float* __restrict__ dec_b,
    float* __restrict__ out)
{
    extern __shared__ __align__(16) float smf[];
    float* xs  = smf + F_XS;    // transposed [k][68]
    float* w1s = smf + F_W1;    // swizzled  [k][128]
    float* h1s = smf + F_H1;    // [row][132]
    float* w2s = smf + F_W2;    // [k][32] (overlaid, staged in phase 1.5)
    float* hs  = smf + F_HS;
    float* ats = smf + F_ATS;
    float* h2s = smf + F_H2S;

    const int t    = threadIdx.x;
    const int warp = t >> 5;
    const int lane = t & 31;
    const int row0 = blockIdx.x * ROWS;

    // ---------------- Phase 0: staging ----------------
    {
        // x -> xs_t transposed with row-XOR swizzle
        const float4* xg = (const float4*)(x + (size_t)row0 * 64);
        #pragma unroll
        for (int i = t; i < 1024; i += NTHREADS) {
            float4 v = __ldg(&xg[i]);
            int row = i >> 4, kc = i & 15;
            int rsw = row ^ ((kc & 7) << 2);
            float* base = xs + kc * 4 * 68 + rsw;
            base[0] = v.x; base[68] = v.y; base[136] = v.z; base[204] = v.w;
        }
        // w1 -> swizzled chunks
        const float4* w1g4 = (const float4*)w1g;
        #pragma unroll
        for (int i = t; i < 2048; i += NTHREADS) {
            int k = i >> 5, c = i & 31;
            ((float4*)w1s)[k * 32 + w1phys(c)] = __ldg(&w1g4[i]);
        }
        // small params
        if (t < 64) {
            smf[FS_MEAN + t] = norm_mean[t];
            smf[FS_INV + t]  = 1.0f / (norm_std[t] + 1e-8f);
            smf[FS_SRCW + t] = src_w[t];
            smf[FS_DSTW + t] = dst_w[t];
        }
        if (t < 128) smf[FS_B1 + t] = b1[t];
        if (t < 32)  { smf[FS_B2 + t] = b2[t]; smf[FS_ENCB + t] = enc_b[t]; }
        if (t < 16)  { smf[FS_SRCB + t] = src_b[t]; smf[FS_DSTB + t] = dst_b[t]; }
        if (t < 256) smf[FS_ENCW + t] = enc_w[t];
        if (t < 192) smf[FS_DECW + (t & 1) * 96 + (t >> 1)] = dec_w[t];
        if (t < 2)   smf[FS_DECB + t] = dec_b[t];
    }
    __syncthreads();

    if (t < 256) {
        // ---------- Phase 1: MLP1  h1 = relu(x @ w1 + b1), 4r x 8c tiles ----------
        const int rg = t >> 4;           // 0..15 -> rows rg*4..+3
        const int tc = t & 15;           // cols tc*8..+7
        const int r0 = rg * 4;
        const int c0 = tc * 8;
        const int p0 = w1phys(2 * tc) * 4;
        const int p1 = w1phys(2 * tc + 1) * 4;

        u64 acc[4][4];
        #pragma unroll
        for (int i = 0; i < 4; i++)
            #pragma unroll
            for (int j = 0; j < 4; j++) acc[i][j] = 0ull;

        #pragma unroll 8
        for (int k = 0; k < 64; k++) {
            int rsw = r0 ^ (((k >> 2) & 7) << 2);
            float4 xa = *(const float4*)&xs[k * 68 + rsw];   // rows r0..r0+3
            ulonglong2 wA = *(const ulonglong2*)&w1s[k * 128 + p0];  // cols c0..c0+3
            ulonglong2 wB = *(const ulonglong2*)&w1s[k * 128 + p1];  // cols c0+4..c0+7
            float xv[4] = {xa.x, xa.y, xa.z, xa.w};
            #pragma unroll
            for (int i = 0; i < 4; i++) {
                u64 ap = pack2(xv[i], xv[i]);
                acc[i][0] = ffma2(ap, wA.x, acc[i][0]);
                acc[i][1] = ffma2(ap, wA.y, acc[i][1]);
                acc[i][2] = ffma2(ap, wB.x, acc[i][2]);
                acc[i][3] = ffma2(ap, wB.y, acc[i][3]);
            }
        }
        float4 bA = *(const float4*)&smf[FS_B1 + c0];
        float4 bB = *(const float4*)&smf[FS_B1 + c0 + 4];
        #pragma unroll
        for (int i = 0; i < 4; i++) {
            float2 u0 = unpack2(acc[i][0]);
            float2 u1 = unpack2(acc[i][1]);
            float2 u2 = unpack2(acc[i][2]);
            float2 u3 = unpack2(acc[i][3]);
            *(float4*)&h1s[(r0 + i) * 132 + c0] =
                make_float4(fmaxf(u0.x + bA.x, 0.f), fmaxf(u0.y + bA.y, 0.f),
                            fmaxf(u1.x + bA.z, 0.f), fmaxf(u1.y + bA.w, 0.f));
            *(float4*)&h1s[(r0 + i) * 132 + c0 + 4] =
                make_float4(fmaxf(u2.x + bB.x, 0.f), fmaxf(u2.y + bB.y, 0.f),
                            fmaxf(u3.x + bB.z, 0.f), fmaxf(u3.y + bB.w, 0.f));
        }
    } else {
        // ---------- Phase 1b: group encoder on warps 8-15 (reads x from global) ----
        #pragma unroll
        for (int it = 0; it < 2; it++) {
            const int task = (t - 256) + it * 256;
            const int row  = task >> 3;
            const int g    = task & 7;
            const int base = g * 8;
            const float4* xr = (const float4*)(x + (size_t)(row0 + row) * 64 + base);
            float4 xa = __ldg(xr), xb = __ldg(xr + 1);
            float xv[8] = {xa.x, xa.y, xa.z, xa.w, xb.x, xb.y, xb.z, xb.w};
            float xn[8];
            #pragma unroll
            for (int f = 0; f < 8; f++)
                xn[f] = (xv[f] - smf[FS_MEAN + base + f]) * smf[FS_INV + base + f];
            ulonglong2 eb = *(const ulonglong2*)&smf[FS_ENCB + g * 4];
            u64 e01 = eb.x, e23 = eb.y;
            #pragma unroll
            for (int f = 0; f < 8; f++) {
                ulonglong2 wf = *(const ulonglong2*)&smf[FS_ENCW + (base + f) * 4];
                u64 xp = pack2(xn[f], xn[f]);
                e01 = ffma2(xp, wf.x, e01);
                e23 = ffma2(xp, wf.y, e23);
            }
            float2 v01 = unpack2(e01), v23 = unpack2(e23);
            *(float4*)&hs[row * SS + g * 4] =
                make_float4(fmaxf(v01.x, 0.f), fmaxf(v01.y, 0.f),
                            fmaxf(v23.x, 0.f), fmaxf(v23.y, 0.f));
        }
    }
    __syncthreads();   // h1, hs ready; xs_t/w1 dead

    if (warp < 4) {
        // ---------- Phase 1.5: warps 0-3 stage w2 (over dead xs_t region) ----------
        const float4* w2g4 = (const float4*)w2g;
        #pragma unroll
        for (int i = t; i < 1024; i += 128) ((float4*)w2s)[i] = __ldg(&w2g4[i]);
        asm volatile("bar.sync 1, 128;" ::: "memory");

        // ---------- Phase 2: MLP2  h2 = relu(h1 @ w2 + b2) on warps 0-3 ----------
        // thread: rows rowg+16i (i=0..3), cols c0..c0+3
        const int rowg = t >> 3;        // 0..15
        const int c0   = (t & 7) * 4;
        u64 a01[4], a23[4];
        #pragma unroll
        for (int i = 0; i < 4; i++) { a01[i] = 0ull; a23[i] = 0ull; }

        #pragma unroll 8
        for (int k = 0; k < 128; k++) {
            ulonglong2 w = *(const ulonglong2*)&w2s[k * 32 + c0];
            #pragma unroll
            for (int i = 0; i < 4; i++) {
                float a = h1s[(rowg + 16 * i) * 132 + k];
                u64 ap = pack2(a, a);
                a01[i] = ffma2(ap, w.x, a01[i]);
                a23[i] = ffma2(ap, w.y, a23[i]);
            }
        }
        float4 bb = *(const float4*)&smf[FS_B2 + c0];
        #pragma unroll
        for (int i = 0; i < 4; i++) {
            float2 u0 = unpack2(a01[i]), u1 = unpack2(a23[i]);
            *(float4*)&h2s[(rowg + 16 * i) * SS + c0] =
                make_float4(fmaxf(u0.x + bb.x, 0.f), fmaxf(u0.y + bb.y, 0.f),
                            fmaxf(u1.x + bb.z, 0.f), fmaxf(u1.y + bb.w, 0.f));
        }
    } else {
        // ---------- Phase 3: attention on warps 4-15 (concurrent with MLP2) ------
        const int w4 = warp - 4;            // 0..11
        const int r2 = lane >> 4, hd = (lane >> 3) & 1, g = lane & 7;
        #pragma unroll
        for (int p = 0; p < 3; p++) {
            const int row = (p * 12 + w4) * 2 + r2;
            if (row < ROWS) {
                float4 hg4 = *(const float4*)&hs[row * SS + g * 4];
                float hge[4] = {hg4.x, hg4.y, hg4.z, hg4.w};

                ulonglong2 sb0 = *(const ulonglong2*)&smf[FS_SRCB + hd * 8];
                ulonglong2 sb1 = *(const ulonglong2*)&smf[FS_SRCB + hd * 8 + 4];
                ulonglong2 db0 = *(const ulonglong2*)&smf[FS_DSTB + hd * 8];
                ulonglong2 db1 = *(const ulonglong2*)&smf[FS_DSTB + hd * 8 + 4];
                u64 sp[4] = {sb0.x, sb0.y, sb1.x, sb1.y};
                u64 dp[4] = {db0.x, db0.y, db1.x, db1.y};
                #pragma unroll
                for (int e = 0; e < 4; e++) {
                    u64 hp = pack2(hge[e], hge[e]);
                    ulonglong2 sv0 = *(const ulonglong2*)&smf[FS_SRCW + e * 16 + hd * 8];
                    ulonglong2 sv1 = *(const ulonglong2*)&smf[FS_SRCW + e * 16 + hd * 8 + 4];
                    ulonglong2 dv0 = *(const ulonglong2*)&smf[FS_DSTW + e * 16 + hd * 8];
                    ulonglong2 dv1 = *(const ulonglong2*)&smf[FS_DSTW + e * 16 + hd * 8 + 4];
                    sp[0] = ffma2(hp, sv0.x, sp[0]); sp[1] = ffma2(hp, sv0.y, sp[1]);
                    sp[2] = ffma2(hp, sv1.x, sp[2]); sp[3] = ffma2(hp, sv1.y, sp[3]);
                    dp[0] = ffma2(hp, dv0.x, dp[0]); dp[1] = ffma2(hp, dv0.y, dp[1]);
                    dp[2] = ffma2(hp, dv1.x, dp[2]); dp[3] = ffma2(hp, dv1.y, dp[3]);
                }
                float sr[8], ds[8];
                #pragma unroll
                for (int j = 0; j < 4; j++) {
                    float2 s = unpack2(sp[j]); sr[2*j] = s.x; sr[2*j+1] = s.y;
                    float2 d = unpack2(dp[j]); ds[2*j] = d.x; ds[2*j+1] = d.y;
                }
                float sc[8];
                #pragma unroll
                for (int k = 0; k < 8; k++) {
                    float s = 0.f;
                    const int srcl = (lane & 24) | k;
                    #pragma unroll
                    for (int a = 0; a < 8; a++)
                        s += sr[a] * __shfl_sync(0xffffffffu, ds[a], srcl);
                    sc[k] = s * 0.35355339059327373f;
                }
                float m = sc[0];
                #pragma unroll
                for (int k = 1; k < 8; k++) m = fmaxf(m, sc[k]);
                float sum = 0.f;
                #pragma unroll
                for (int k = 0; k < 8; k++) { sc[k] = __expf(sc[k] - m); sum += sc[k]; }
                const float invs = 1.f / sum;

                u64 a01 = 0ull, a23 = 0ull;
                #pragma unroll
                for (int k = 0; k < 8; k++) {
                    float pr = sc[k] * invs;
                    u64 pp = pack2(pr, pr);
                    ulonglong2 hv = *(const ulonglong2*)&hs[row * SS + k * 4];
                    a01 = ffma2(pp, hv.x, a01);
                    a23 = ffma2(pp, hv.y, a23);
                }
                float2 u0 = unpack2(a01), u1 = unpack2(a23);
                float av[4] = {u0.x, u0.y, u1.x, u1.y};
                #pragma unroll
                for (int e = 0; e < 4; e++)
                    av[e] += __shfl_xor_sync(0xffffffffu, av[e], 8);
                if (hd == 0)
                    *(float4*)&ats[row * SS + g * 4] = make_float4(av[0], av[1], av[2], av[3]);
            }
        }
    }
    __syncthreads();   // h2s, ats ready

    // ---------------- Phase 4: decoder ----------------
    if (t < ROWS * 2) {
        const int row = t >> 1;
        const int o   = t & 1;
        float acc = smf[FS_DECB + o];
        const float* wv = smf + FS_DECW + o * 96;
        const float* srcs[3] = {h2s, hs, ats};
        #pragma unroll
        for (int s = 0; s < 3; s++) {
            const float* sv = srcs[s] + row * SS;
            const int off = s * 32;
            #pragma unroll
            for (int j = 0; j < 8; j++) {
                float4 v  = *(const float4*)&sv[j * 4];
                float4 wa = *(const float4*)&wv[off + j * 4];
                acc += v.x * wa.x + v.y * wa.y + v.z * wa.z + v.w * wa.w;
            }
        }
        out[(size_t)(row0 + row) * 2 + o] = acc;
    }
}

extern "C" void kernel_launch(void* const* d_in, const int* in_sizes, int n_in,
                              void* d_out, int out_size)
{
    const float* x         = (const float*)d_in[0];
    const float* norm_mean = (const float*)d_in[1];
    const float* norm_std  = (const float*)d_in[2];
    const float* w1        = (const float*)d_in[3];
    const float* b1        = (const float*)d_in[4];
    const float* w2        = (const float*)d_in[5];
    const float* b2        = (const float*)d_in[6];
    const float* enc_w     = (const float*)d_in[7];
    const float* enc_b     = (const float*)d_in[8];
    const float* src_w     = (const float*)d_in[9];
    const float* src_b     = (const float*)d_in[10];
    const float* dst_w     = (const float*)d_in[11];
    const float* dst_b     = (const float*)d_in[12];
    const float* dec_w     = (const float*)d_in[13];
    const float* dec_b     = (const float*)d_in[14];
    float* out = (float*)d_out;

    cudaFuncSetAttribute(ggat_kernel,
                         cudaFuncAttributeMaxDynamicSharedMemorySize, SMEM_BYTES);
    ggat_kernel<<<NBLOCKS, NTHREADS, SMEM_BYTES>>>(
        x, norm_mean, norm_std, w1, b1, w2, b2,
        enc_w, enc_b, src_w, src_b, dst_w, dst_b, dec_w, dec_b, out);
}